// round 10
// baseline (speedup 1.0000x reference)
#include <cuda_runtime.h>
#include <math.h>

#define DD 64
#define KK 512

typedef unsigned long long u64;

__device__ __forceinline__ u64 pk2(float a, float b) {
    u64 r; asm("mov.b64 %0,{%1,%2};" : "=l"(r) : "f"(a), "f"(b)); return r;
}
__device__ __forceinline__ void upk2(u64 v, float& a, float& b) {
    asm("mov.b64 {%0,%1},%2;" : "=f"(a), "=f"(b) : "l"(v));
}
__device__ __forceinline__ u64 fma2(u64 a, u64 b, u64 c) {
    u64 d; asm("fma.rn.f32x2 %0,%1,%2,%3;" : "=l"(d) : "l"(a), "l"(b), "l"(c)); return d;
}
__device__ __forceinline__ u64 add2(u64 a, u64 b) {
    u64 d; asm("add.rn.f32x2 %0,%1,%2;" : "=l"(d) : "l"(a), "l"(b)); return d;
}

// Reference-style squared-norm (cold path, R6-validated).
__device__ __forceinline__ float ref_norm2(const float* __restrict__ r) {
    float a[32];
    #pragma unroll
    for (int j = 0; j < 32; j++)
        a[j] = __fadd_rn(__fmul_rn(r[j], r[j]), __fmul_rn(r[j + 32], r[j + 32]));
    #pragma unroll
    for (int j = 0; j < 16; j++) a[j] = __fadd_rn(a[j], a[j + 16]);
    #pragma unroll
    for (int j = 0; j < 8; j++)  a[j] = __fadd_rn(a[j], a[j + 8]);
    #pragma unroll
    for (int j = 0; j < 4; j++)  a[j] = __fadd_rn(a[j], a[j + 4]);
    a[0] = __fadd_rn(a[0], a[2]); a[1] = __fadd_rn(a[1], a[3]);
    return __fadd_rn(a[0], a[1]);
}

#define SMEM_MAIN ((KK * DD + 2 * KK) * 4)
#define TIE_TAU 3e-5f

// fast sqrt via MUFU.RSQ (rel err ~2e-7); clamp avoids 0*inf=NaN at d2=0
__device__ __forceinline__ float fast_negsqrt(float d2) {
    float d2c = fmaxf(d2, 1e-30f);
    return -(d2c * rsqrtf(d2c));
}

__global__ __launch_bounds__(256, 1)
void sq_main(const float* __restrict__ x, const float* __restrict__ w,
             float* __restrict__ outq, float* __restrict__ outidx, int N) {
    extern __shared__ float smem[];
    float* wsh  = smem;                 // KK*DD
    float* w2sh = smem + KK * DD;       // KK (hot path)
    float* w2em = smem + KK * DD + KK;  // KK (reference-emulated)

    for (int i = threadIdx.x; i < KK * DD / 4; i += blockDim.x) {
        ((float4*)wsh)[i] = ((const float4*)w)[i];
    }
    __syncthreads();
    for (int k = threadIdx.x; k < KK; k += blockDim.x) {
        const float* r = wsh + k * DD;
        float s = 0.f;
        #pragma unroll 16
        for (int d = 0; d < DD; d++) s += r[d] * r[d];
        w2sh[k] = s;
        w2em[k] = ref_norm2(r);
    }
    __syncthreads();

    int row    = blockIdx.x * blockDim.x + threadIdx.x;
    int stride = gridDim.x * blockDim.x;

    for (; row < N; row += stride) {
        const float4* xr = (const float4*)(x + (size_t)row * DD);
        u64 xp[DD / 2];
        float x2 = 0.f;
        #pragma unroll
        for (int i = 0; i < DD / 4; i++) {
            float4 v = xr[i];
            xp[2 * i]     = pk2(v.x, v.y);
            xp[2 * i + 1] = pk2(v.z, v.w);
            x2 += v.x * v.x + v.y * v.y + v.z * v.z + v.w * v.w;
        }

        u64 accp[DD / 2];
        #pragma unroll
        for (int i = 0; i < DD / 2; i++) accp[i] = 0ull;

        float s = 0.f;
        float dist1 = -3.4e38f, dist2 = -3.4e38f;
        int   bestk = 0;

        // Two k's per iteration: independent dot/rsqrt/exp chains overlap,
        // accumulate fills the MUFU latency. W reloaded per phase (LDS
        // broadcast is cheap; keeps regs ~175, no spills).
        #pragma unroll 1
        for (int k = 0; k < KK; k += 2) {
            const u64* w0 = (const u64*)(wsh + (k << 6));
            const u64* w1 = w0 + 32;

            u64 a0 = 0ull, a1 = 0ull, a2 = 0ull, a3 = 0ull;
            u64 b0 = 0ull, b1 = 0ull, b2 = 0ull, b3 = 0ull;
            #pragma unroll
            for (int i = 0; i < 32; i += 4) {
                a0 = fma2(xp[i],     w0[i],     a0);
                a1 = fma2(xp[i + 1], w0[i + 1], a1);
                a2 = fma2(xp[i + 2], w0[i + 2], a2);
                a3 = fma2(xp[i + 3], w0[i + 3], a3);
                b0 = fma2(xp[i],     w1[i],     b0);
                b1 = fma2(xp[i + 1], w1[i + 1], b1);
                b2 = fma2(xp[i + 2], w1[i + 2], b2);
                b3 = fma2(xp[i + 3], w1[i + 3], b3);
            }
            u64 ta = add2(add2(a0, a1), add2(a2, a3));
            u64 tb = add2(add2(b0, b1), add2(b2, b3));
            float al, ah, bl, bh;
            upk2(ta, al, ah);
            upk2(tb, bl, bh);
            float dot0 = al + ah;
            float dot1 = bl + bh;

            float d20 = fmaxf(__fsub_rn(__fadd_rn(x2, w2sh[k]),     2.f * dot0), 0.f);
            float d21 = fmaxf(__fsub_rn(__fadd_rn(x2, w2sh[k + 1]), 2.f * dot1), 0.f);
            float dist0 = fast_negsqrt(d20);
            float dist1v = fast_negsqrt(d21);
            float e0 = __expf(dist0);          // dist in [-13,0]: shift-0 softmax safe
            float e1 = __expf(dist1v);
            s += (e0 + e1);

            if (dist0 > dist1) { dist2 = dist1; dist1 = dist0; bestk = k; }
            else if (dist0 > dist2) { dist2 = dist0; }
            if (dist1v > dist1) { dist2 = dist1; dist1 = dist1v; bestk = k + 1; }
            else if (dist1v > dist2) { dist2 = dist1v; }

            u64 e0p = pk2(e0, e0);
            u64 e1p = pk2(e1, e1);
            #pragma unroll
            for (int i = 0; i < 32; i++) {
                accp[i] = fma2(e1p, w1[i], fma2(e0p, w0[i], accp[i]));
            }
        }

        float inv = 1.f / s;
        float4* qo = (float4*)(outq + (size_t)row * DD);
        #pragma unroll
        for (int i = 0; i < DD / 4; i++) {
            float a, b, c, d;
            upk2(accp[2 * i], a, b);
            upk2(accp[2 * i + 1], c, d);
            float4 v; v.x = a * inv; v.y = b * inv; v.z = c * inv; v.w = d * inv;
            qo[i] = v;
        }

        // Cold path (rare, R6-validated): bit-faithful reference emulation.
        if (dist1 - dist2 < TIE_TAU) {
            const float* xrow = x + (size_t)row * DD;
            float xf[DD];
            #pragma unroll
            for (int d = 0; d < DD; d++) xf[d] = xrow[d];
            float x2em = ref_norm2(xf);

            float distbuf[KK];
            float m = -3.4e38f;
            #pragma unroll 1
            for (int k = 0; k < KK; k++) {
                const float* r = wsh + k * DD;
                float acc = 0.f;
                #pragma unroll
                for (int d = 0; d < DD; d++) acc = __fmaf_rn(xf[d], r[d], acc);
                float d2 = __fsub_rn(__fadd_rn(x2em, w2em[k]), __fmul_rn(2.f, acc));
                if (d2 < 0.f) d2 = 0.f;
                float dist = -__fsqrt_rn(d2);
                distbuf[k] = dist;
                m = fmaxf(m, dist);
            }
            float ssum = 0.f;
            #pragma unroll 1
            for (int k = 0; k < KK; k++)
                ssum = __fadd_rn(ssum, (float)exp((double)__fsub_rn(distbuf[k], m)));
            float bestv = -1.f;
            int bk = 0;
            #pragma unroll 1
            for (int k = 0; k < KK; k++) {
                float e = (float)exp((double)__fsub_rn(distbuf[k], m));
                float v = __fdiv_rn(e, ssum);
                if (v > bestv) { bestv = v; bk = k; }
            }
            bestk = bk;
        }

        if (outidx) outidx[row] = (float)bestk;
    }
}

// Ortho loss: mean((norm_w @ norm_w^T)^2) - 1/K
#define OSTRIDE 65
#define SMEM_ORTHO (KK * OSTRIDE * 4)

__global__ __launch_bounds__(256)
void sq_ortho(const float* __restrict__ w, float* __restrict__ loss) {
    extern __shared__ float sm[];
    for (int idx = threadIdx.x; idx < KK * DD; idx += blockDim.x) {
        int r = idx >> 6, c = idx & 63;
        sm[r * OSTRIDE + c] = w[idx];
    }
    __syncthreads();
    for (int k = threadIdx.x; k < KK; k += blockDim.x) {
        float* r = sm + k * OSTRIDE;
        float n2 = 0.f;
        #pragma unroll 16
        for (int d = 0; d < DD; d++) n2 += r[d] * r[d];
        float inv = 1.f / fmaxf(sqrtf(n2), 1e-12f);
        #pragma unroll 16
        for (int d = 0; d < DD; d++) r[d] *= inv;
    }
    __syncthreads();

    float local = 0.f;
    int total = KK * KK;
    for (int p = blockIdx.x * blockDim.x + threadIdx.x; p < total;
         p += gridDim.x * blockDim.x) {
        int i = p >> 9, j = p & (KK - 1);
        const float* ri = sm + i * OSTRIDE;
        const float* rj = sm + j * OSTRIDE;
        float c = 0.f;
        #pragma unroll 16
        for (int d = 0; d < DD; d++) c += ri[d] * rj[d];
        local += c * c;
    }
    for (int off = 16; off > 0; off >>= 1)
        local += __shfl_down_sync(0xFFFFFFFF, local, off);
    __shared__ float red[8];
    int wid = threadIdx.x >> 5, lid = threadIdx.x & 31;
    if (lid == 0) red[wid] = local;
    __syncthreads();
    if (threadIdx.x == 0) {
        float bs = 0.f;
        for (int i = 0; i < (int)(blockDim.x >> 5); i++) bs += red[i];
        atomicAdd(loss, bs * (1.f / ((float)KK * (float)KK)));
        if (blockIdx.x == 0) atomicAdd(loss, -1.f / (float)KK);
    }
}

extern "C" void kernel_launch(void* const* d_in, const int* in_sizes, int n_in,
                              void* d_out, int out_size) {
    const float* x = (const float*)d_in[0];
    const float* w = (const float*)d_in[1];
    int N = in_sizes[0] / DD;

    float* out = (float*)d_out;
    size_t qn = (size_t)N * DD;
    float* outloss = nullptr;
    float* outidx  = nullptr;
    long long os = (long long)out_size;
    if (os >= (long long)(qn + 1 + (size_t)N)) {         // [quantized | loss | indices]
        outloss = out + qn;
        outidx  = out + qn + 1;
    } else if (os == (long long)(qn + (size_t)N)) {      // [quantized | indices]
        outidx = out + qn;
    } else if (os == (long long)(qn + 1)) {              // [quantized | loss]
        outloss = out + qn;
    }

    cudaFuncSetAttribute(sq_main,  cudaFuncAttributeMaxDynamicSharedMemorySize, SMEM_MAIN);
    cudaFuncSetAttribute(sq_ortho, cudaFuncAttributeMaxDynamicSharedMemorySize, SMEM_ORTHO);

    int grid = (N + 255) / 256;
    sq_main<<<grid, 256, SMEM_MAIN>>>(x, w, out, outidx, N);

    if (outloss) {
        cudaMemsetAsync(outloss, 0, sizeof(float));
        sq_ortho<<<128, 256, SMEM_ORTHO>>>(w, outloss);
    }
}

// round 13
// speedup vs baseline: 1.1191x; 1.1191x over previous
#include <cuda_runtime.h>
#include <math.h>
#include <stdint.h>

#define DD 64
#define KK 512
#define WSTRIDE 68          // 68 mod 32 = 4 -> conflict-free B-frag loads
#define XSTRIDE 68
#define ROWS_PER_CTA 128
#define NT (KK / 8)         // 64 n-tiles
#define TIE_TAU 3e-5f

// SMEM layout (floats)
#define SM_W    0
#define SM_X    (KK * WSTRIDE)                    // 34816
#define SM_W2   (SM_X + ROWS_PER_CTA * XSTRIDE)   // +8704
#define SM_W2EM (SM_W2 + KK)
#define SM_PS   (SM_W2EM + KK)
#define SMEM_FLOATS (SM_PS + 8 * 16 * 9)
#define SMEM_MAIN (SMEM_FLOATS * 4)

__device__ __forceinline__ uint32_t f2tf(float x) {
    uint32_t r; asm("cvt.rna.tf32.f32 %0,%1;" : "=r"(r) : "f"(x)); return r;
}

__device__ __forceinline__ void mma8(float& c0, float& c1, float& c2, float& c3,
                                     uint32_t a0, uint32_t a1, uint32_t a2, uint32_t a3,
                                     uint32_t b0, uint32_t b1) {
    asm volatile(
        "mma.sync.aligned.m16n8k8.row.col.f32.tf32.tf32.f32 "
        "{%0,%1,%2,%3},{%4,%5,%6,%7},{%8,%9},{%0,%1,%2,%3};"
        : "+f"(c0), "+f"(c1), "+f"(c2), "+f"(c3)
        : "r"(a0), "r"(a1), "r"(a2), "r"(a3), "r"(b0), "r"(b1));
}

// Reference-style squared-norm (cold path, R6-validated).
__device__ __forceinline__ float ref_norm2(const float* __restrict__ r) {
    float a[32];
    #pragma unroll
    for (int j = 0; j < 32; j++)
        a[j] = __fadd_rn(__fmul_rn(r[j], r[j]), __fmul_rn(r[j + 32], r[j + 32]));
    #pragma unroll
    for (int j = 0; j < 16; j++) a[j] = __fadd_rn(a[j], a[j + 16]);
    #pragma unroll
    for (int j = 0; j < 8; j++)  a[j] = __fadd_rn(a[j], a[j + 8]);
    #pragma unroll
    for (int j = 0; j < 4; j++)  a[j] = __fadd_rn(a[j], a[j + 4]);
    a[0] = __fadd_rn(a[0], a[2]); a[1] = __fadd_rn(a[1], a[3]);
    return __fadd_rn(a[0], a[1]);
}

__device__ __forceinline__ float fast_negsqrt(float d2) {
    float d2c = fmaxf(d2, 1e-30f);
    return -(d2c * rsqrtf(d2c));
}

// Cold path (rare, R6-validated): bit-faithful reference emulation.
__device__ __noinline__ int cold_resolve(const float* __restrict__ xr,
                                         const float* __restrict__ wsh,
                                         const float* __restrict__ w2em) {
    float xf[DD];
    #pragma unroll
    for (int d = 0; d < DD; d++) xf[d] = xr[d];
    float x2em = ref_norm2(xf);

    float distbuf[KK];
    float m = -3.4e38f;
    #pragma unroll 1
    for (int k = 0; k < KK; k++) {
        const float* r = wsh + k * WSTRIDE;
        float acc = 0.f;
        #pragma unroll
        for (int d = 0; d < DD; d++) acc = __fmaf_rn(xf[d], r[d], acc);
        float d2 = __fsub_rn(__fadd_rn(x2em, w2em[k]), __fmul_rn(2.f, acc));
        if (d2 < 0.f) d2 = 0.f;
        float dist = -__fsqrt_rn(d2);
        distbuf[k] = dist;
        m = fmaxf(m, dist);
    }
    float ssum = 0.f;
    #pragma unroll 1
    for (int k = 0; k < KK; k++)
        ssum = __fadd_rn(ssum, (float)exp((double)__fsub_rn(distbuf[k], m)));
    float bestv = -1.f;
    int bk = 0;
    #pragma unroll 1
    for (int k = 0; k < KK; k++) {
        float e = (float)exp((double)__fsub_rn(distbuf[k], m));
        float v = __fdiv_rn(e, ssum);
        if (v > bestv) { bestv = v; bk = k; }
    }
    return bk;
}

__global__ __launch_bounds__(256, 1)
void sq_main(const float* __restrict__ x, const float* __restrict__ w,
             float* __restrict__ outq, float* __restrict__ outidx, int N) {
    extern __shared__ float sm[];
    float* wsh  = sm + SM_W;
    float* xsh  = sm + SM_X;
    float* w2sh = sm + SM_W2;
    float* w2em = sm + SM_W2EM;

    int tid = threadIdx.x, wid = tid >> 5, lane = tid & 31;
    int g = lane >> 2, t = lane & 3;
    int base = blockIdx.x * ROWS_PER_CTA;

    // Stage W [512,64] -> padded stride 68
    for (int i = tid; i < KK * DD / 4; i += 256) {
        float4 v = ((const float4*)w)[i];
        int k = i >> 4, c = (i & 15) * 4;
        float* dst = wsh + k * WSTRIDE + c;
        dst[0] = v.x; dst[1] = v.y; dst[2] = v.z; dst[3] = v.w;
    }
    // Stage x tile [128,64] -> padded stride 68
    for (int i = tid; i < ROWS_PER_CTA * DD / 4; i += 256) {
        int r = i >> 4, c = (i & 15) * 4;
        float4 v = make_float4(0.f, 0.f, 0.f, 0.f);
        if (base + r < N) v = ((const float4*)(x + (size_t)(base + r) * DD))[i & 15];
        float* dst = xsh + r * XSTRIDE + c;
        dst[0] = v.x; dst[1] = v.y; dst[2] = v.z; dst[3] = v.w;
    }
    __syncthreads();
    for (int k = tid; k < KK; k += 256) {
        const float* r = wsh + k * WSTRIDE;
        float s = 0.f;
        #pragma unroll 16
        for (int d = 0; d < DD; d++) s += r[d] * r[d];
        w2sh[k] = s;
        w2em[k] = ref_norm2(r);
    }
    __syncthreads();

    int wrow = wid * 16;
    const float* r0p = xsh + (wrow + g) * XSTRIDE;
    const float* r1p = xsh + (wrow + g + 8) * XSTRIDE;

    // A fragments (x rows) with tf32 hi/lo split, all 8 k-tiles
    uint32_t Ah[8][4], Al[8][4];
    #pragma unroll
    for (int kt = 0; kt < 8; kt++) {
        float a0 = r0p[kt * 8 + t],     a1 = r1p[kt * 8 + t];
        float a2 = r0p[kt * 8 + t + 4], a3 = r1p[kt * 8 + t + 4];
        Ah[kt][0] = f2tf(a0); Al[kt][0] = f2tf(a0 - __uint_as_float(Ah[kt][0]));
        Ah[kt][1] = f2tf(a1); Al[kt][1] = f2tf(a1 - __uint_as_float(Ah[kt][1]));
        Ah[kt][2] = f2tf(a2); Al[kt][2] = f2tf(a2 - __uint_as_float(Ah[kt][2]));
        Ah[kt][3] = f2tf(a3); Al[kt][3] = f2tf(a3 - __uint_as_float(Ah[kt][3]));
    }
    // x2 per row via quad partials
    float x2r0, x2r1;
    {
        float p0 = 0.f, p1 = 0.f;
        #pragma unroll
        for (int d = t; d < DD; d += 4) {
            p0 = fmaf(r0p[d], r0p[d], p0);
            p1 = fmaf(r1p[d], r1p[d], p1);
        }
        p0 += __shfl_xor_sync(0xFFFFFFFFu, p0, 1);
        p0 += __shfl_xor_sync(0xFFFFFFFFu, p0, 2);
        p1 += __shfl_xor_sync(0xFFFFFFFFu, p1, 1);
        p1 += __shfl_xor_sync(0xFFFFFFFFu, p1, 2);
        x2r0 = p0; x2r1 = p1;
    }

    float Q[8][4];
    #pragma unroll
    for (int dt = 0; dt < 8; dt++) { Q[dt][0] = Q[dt][1] = Q[dt][2] = Q[dt][3] = 0.f; }

    float sA = 0.f, sB = 0.f;
    float d1A = -3.4e38f, d2A = -3.4e38f, d1B = -3.4e38f, d2B = -3.4e38f;
    int kA = 0, kB = 0;
    float* ps = sm + SM_PS + wid * 144;   // 16x9 per-warp scratch

    #pragma unroll 1
    for (int nt = 0; nt < NT; nt++) {
        // GEMM1: dots for 8 codes (3xTF32)
        float c0 = 0.f, c1 = 0.f, c2 = 0.f, c3 = 0.f;
        const float* bp = wsh + (nt * 8 + g) * WSTRIDE;
        #pragma unroll
        for (int kt = 0; kt < 8; kt++) {
            float b0f = bp[kt * 8 + t], b1f = bp[kt * 8 + t + 4];
            uint32_t b0h = f2tf(b0f), b1h = f2tf(b1f);
            uint32_t b0l = f2tf(b0f - __uint_as_float(b0h));
            uint32_t b1l = f2tf(b1f - __uint_as_float(b1h));
            mma8(c0, c1, c2, c3, Ah[kt][0], Ah[kt][1], Ah[kt][2], Ah[kt][3], b0h, b1h);
            mma8(c0, c1, c2, c3, Al[kt][0], Al[kt][1], Al[kt][2], Al[kt][3], b0h, b1h);
            mma8(c0, c1, c2, c3, Ah[kt][0], Ah[kt][1], Ah[kt][2], Ah[kt][3], b0l, b1l);
        }
        int n0 = nt * 8 + 2 * t, n1 = n0 + 1;
        float w20 = w2sh[n0], w21 = w2sh[n1];
        float di0 = fast_negsqrt(fmaxf(x2r0 + w20 - 2.f * c0, 0.f));
        float di1 = fast_negsqrt(fmaxf(x2r0 + w21 - 2.f * c1, 0.f));
        float di2 = fast_negsqrt(fmaxf(x2r1 + w20 - 2.f * c2, 0.f));
        float di3 = fast_negsqrt(fmaxf(x2r1 + w21 - 2.f * c3, 0.f));
        float e0 = __expf(di0), e1 = __expf(di1), e2 = __expf(di2), e3 = __expf(di3);
        sA += e0 + e1; sB += e2 + e3;

        if (di0 > d1A) { d2A = d1A; d1A = di0; kA = n0; } else if (di0 > d2A) d2A = di0;
        if (di1 > d1A) { d2A = d1A; d1A = di1; kA = n1; } else if (di1 > d2A) d2A = di1;
        if (di2 > d1B) { d2B = d1B; d1B = di2; kB = n0; } else if (di2 > d2B) d2B = di2;
        if (di3 > d1B) { d2B = d1B; d1B = di3; kB = n1; } else if (di3 > d2B) d2B = di3;

        // P tile through SMEM: C-layout -> A-layout re-fragmentation
        __syncwarp();
        ps[g * 9 + 2 * t]           = e0;
        ps[g * 9 + 2 * t + 1]       = e1;
        ps[(g + 8) * 9 + 2 * t]     = e2;
        ps[(g + 8) * 9 + 2 * t + 1] = e3;
        __syncwarp();
        float p0f = ps[g * 9 + t],       p1f = ps[(g + 8) * 9 + t];
        float p2f = ps[g * 9 + t + 4],   p3f = ps[(g + 8) * 9 + t + 4];
        uint32_t p0h = f2tf(p0f), p0l = f2tf(p0f - __uint_as_float(p0h));
        uint32_t p1h = f2tf(p1f), p1l = f2tf(p1f - __uint_as_float(p1h));
        uint32_t p2h = f2tf(p2f), p2l = f2tf(p2f - __uint_as_float(p2h));
        uint32_t p3h = f2tf(p3f), p3l = f2tf(p3f - __uint_as_float(p3h));

        // GEMM2: Q += P @ W (3xTF32), B[k=code][n=dim] = wsh[code*WSTRIDE + dim]
        const float* b2p = wsh + (nt * 8 + t) * WSTRIDE;
        #pragma unroll
        for (int dt = 0; dt < 8; dt++) {
            float b0f = b2p[dt * 8 + g];
            float b1f = b2p[4 * WSTRIDE + dt * 8 + g];
            uint32_t b0h = f2tf(b0f), b1h = f2tf(b1f);
            uint32_t b0l = f2tf(b0f - __uint_as_float(b0h));
            uint32_t b1l = f2tf(b1f - __uint_as_float(b1h));
            mma8(Q[dt][0], Q[dt][1], Q[dt][2], Q[dt][3], p0h, p1h, p2h, p3h, b0h, b1h);
            mma8(Q[dt][0], Q[dt][1], Q[dt][2], Q[dt][3], p0l, p1l, p2l, p3l, b0h, b1h);
            mma8(Q[dt][0], Q[dt][1], Q[dt][2], Q[dt][3], p0h, p1h, p2h, p3h, b0l, b1l);
        }
    }

    // Reduce softmax sums and top-2 across the 4-lane quad
    sA += __shfl_xor_sync(0xFFFFFFFFu, sA, 1);
    sA += __shfl_xor_sync(0xFFFFFFFFu, sA, 2);
    sB += __shfl_xor_sync(0xFFFFFFFFu, sB, 1);
    sB += __shfl_xor_sync(0xFFFFFFFFu, sB, 2);
    #pragma unroll
    for (int m = 1; m <= 2; m <<= 1) {
        float o1 = __shfl_xor_sync(0xFFFFFFFFu, d1A, m);
        float o2 = __shfl_xor_sync(0xFFFFFFFFu, d2A, m);
        int   ok = __shfl_xor_sync(0xFFFFFFFFu, kA, m);
        if (o1 > d1A) { d2A = fmaxf(d1A, o2); d1A = o1; kA = ok; }
        else          { d2A = fmaxf(d2A, o1); }
        o1 = __shfl_xor_sync(0xFFFFFFFFu, d1B, m);
        o2 = __shfl_xor_sync(0xFFFFFFFFu, d2B, m);
        ok = __shfl_xor_sync(0xFFFFFFFFu, kB, m);
        if (o1 > d1B) { d2B = fmaxf(d1B, o2); d1B = o1; kB = ok; }
        else          { d2B = fmaxf(d2B, o1); }
    }

    float invA = 1.f / sA, invB = 1.f / sB;
    int row0 = base + wrow + g, row1 = row0 + 8;
    if (row0 < N) {
        #pragma unroll
        for (int dt = 0; dt < 8; dt++) {
            float2 v0; v0.x = Q[dt][0] * invA; v0.y = Q[dt][1] * invA;
            *(float2*)(outq + (size_t)row0 * DD + dt * 8 + 2 * t) = v0;
        }
    }
    if (row1 < N) {
        #pragma unroll
        for (int dt = 0; dt < 8; dt++) {
            float2 v1; v1.x = Q[dt][2] * invB; v1.y = Q[dt][3] * invB;
            *(float2*)(outq + (size_t)row1 * DD + dt * 8 + 2 * t) = v1;
        }
    }

    if (outidx && t == 0) {
        if (row0 < N) {
            int bk = kA;
            if (d1A - d2A < TIE_TAU) bk = cold_resolve(r0p, wsh, w2em);
            outidx[row0] = (float)bk;
        }
        if (row1 < N) {
            int bk = kB;
            if (d1B - d2B < TIE_TAU) bk = cold_resolve(r1p, wsh, w2em);
            outidx[row1] = (float)bk;
        }
    }
}

// Ortho loss: mean((norm_w @ norm_w^T)^2) - 1/K
#define OSTRIDE 65
#define SMEM_ORTHO (KK * OSTRIDE * 4)

__global__ __launch_bounds__(256)
void sq_ortho(const float* __restrict__ w, float* __restrict__ loss) {
    extern __shared__ float sm[];
    for (int idx = threadIdx.x; idx < KK * DD; idx += blockDim.x) {
        int r = idx >> 6, c = idx & 63;
        sm[r * OSTRIDE + c] = w[idx];
    }
    __syncthreads();
    for (int k = threadIdx.x; k < KK; k += blockDim.x) {
        float* r = sm + k * OSTRIDE;
        float n2 = 0.f;
        #pragma unroll 16
        for (int d = 0; d < DD; d++) n2 += r[d] * r[d];
        float inv = 1.f / fmaxf(sqrtf(n2), 1e-12f);
        #pragma unroll 16
        for (int d = 0; d < DD; d++) r[d] *= inv;
    }
    __syncthreads();

    float local = 0.f;
    int total = KK * KK;
    for (int p = blockIdx.x * blockDim.x + threadIdx.x; p < total;
         p += gridDim.x * blockDim.x) {
        int i = p >> 9, j = p & (KK - 1);
        const float* ri = sm + i * OSTRIDE;
        const float* rj = sm + j * OSTRIDE;
        float c = 0.f;
        #pragma unroll 16
        for (int d = 0; d < DD; d++) c += ri[d] * rj[d];
        local += c * c;
    }
    for (int off = 16; off > 0; off >>= 1)
        local += __shfl_down_sync(0xFFFFFFFF, local, off);
    __shared__ float red[8];
    int wid = threadIdx.x >> 5, lid = threadIdx.x & 31;
    if (lid == 0) red[wid] = local;
    __syncthreads();
    if (threadIdx.x == 0) {
        float bs = 0.f;
        for (int i = 0; i < (int)(blockDim.x >> 5); i++) bs += red[i];
        atomicAdd(loss, bs * (1.f / ((float)KK * (float)KK)));
        if (blockIdx.x == 0) atomicAdd(loss, -1.f / (float)KK);
    }
}

extern "C" void kernel_launch(void* const* d_in, const int* in_sizes, int n_in,
                              void* d_out, int out_size) {
    const float* x = (const float*)d_in[0];
    const float* w = (const float*)d_in[1];
    int N = in_sizes[0] / DD;

    float* out = (float*)d_out;
    size_t qn = (size_t)N * DD;
    float* outloss = nullptr;
    float* outidx  = nullptr;
    long long os = (long long)out_size;
    if (os >= (long long)(qn + 1 + (size_t)N)) {         // [quantized | loss | indices]
        outloss = out + qn;
        outidx  = out + qn + 1;
    } else if (os == (long long)(qn + (size_t)N)) {      // [quantized | indices]
        outidx = out + qn;
    } else if (os == (long long)(qn + 1)) {              // [quantized | loss]
        outloss = out + qn;
    }

    cudaFuncSetAttribute(sq_main,  cudaFuncAttributeMaxDynamicSharedMemorySize, SMEM_MAIN);
    cudaFuncSetAttribute(sq_ortho, cudaFuncAttributeMaxDynamicSharedMemorySize, SMEM_ORTHO);

    int grid = (N + ROWS_PER_CTA - 1) / ROWS_PER_CTA;
    sq_main<<<grid, 256, SMEM_MAIN>>>(x, w, out, outidx, N);

    if (outloss) {
        cudaMemsetAsync(outloss, 0, sizeof(float));
        sq_ortho<<<128, 256, SMEM_ORTHO>>>(w, outloss);
    }
}